// round 1
// baseline (speedup 1.0000x reference)
#include <cuda_runtime.h>
#include <cstdint>

// Problem constants
#define B_   32
#define C_   256
#define H_   58
#define W_   58
#define OC_  256
#define KH_  3
#define KW_  3
#define HO_  56
#define WO_  56
#define HW_  (H_*W_)            // 3364
#define NWORDS 8                // 256 channels / 32 bits
#define CN_  2304               // C*KH*KW
#define NINPUT 861184.0f        // C*H*W (alpha normalizer)

// Scratch (device globals; no allocations allowed)
__device__ unsigned g_xpack[B_ * HW_ * NWORDS];        // [b][y][x][w]  3.44 MB
__device__ unsigned g_wpack[OC_ * KH_ * KW_ * NWORDS]; // [o][k][w]     73.7 KB
__device__ float    g_alpha[OC_];

// ---------------------------------------------------------------------------
// Pass 1: pack binary activations over the channel dimension.
// grid = (B_*NWORDS, ceil(HW_/256)), block = 256.
// Each thread builds one 32-bit word (32 channels) for one spatial position.
// Loads are fully coalesced (warp spans 32 consecutive positions per channel).
// ---------------------------------------------------------------------------
__global__ void pack_x_kernel(const float* __restrict__ x) {
    int bw = blockIdx.x;
    int b  = bw >> 3;
    int w  = bw & 7;
    int pos = blockIdx.y * blockDim.x + threadIdx.x;
    if (pos >= HW_) return;

    const float* xp = x + ((size_t)(b * C_ + w * 32) * HW_) + pos;
    unsigned bits = 0;
#pragma unroll
    for (int c = 0; c < 32; c++) {
        float v = __ldg(xp + (size_t)c * HW_);
        bits |= (v > 0.5f ? 1u : 0u) << c;
    }
    g_xpack[((size_t)b * HW_ + pos) * NWORDS + w] = bits;
}

// ---------------------------------------------------------------------------
// Pass 2: pack binarized weights (ballot over channel lanes) + alpha per filter.
// grid = OC_, block = 256 (one thread per input channel).
// ---------------------------------------------------------------------------
__global__ void pack_w_kernel(const float* __restrict__ wgt) {
    int o = blockIdx.x;
    int c = threadIdx.x;
    int lane = c & 31;
    int wrp  = c >> 5;

    const float* wp = wgt + (size_t)(o * C_ + c) * (KH_ * KW_);
    float asum = 0.f;
#pragma unroll
    for (int k = 0; k < KH_ * KW_; k++) {
        float v = wp[k];
        asum += fabsf(v);
        unsigned word = __ballot_sync(0xffffffffu, v >= 0.f);
        if (lane == 0) g_wpack[(o * 9 + k) * NWORDS + wrp] = word;
    }

    __shared__ float red[256];
    red[c] = asum;
    __syncthreads();
#pragma unroll
    for (int s = 128; s > 0; s >>= 1) {
        if (c < s) red[c] += red[c + s];
        __syncthreads();
    }
    if (c == 0) g_alpha[o] = red[0] / NINPUT;
}

// ---------------------------------------------------------------------------
// Pass 3: XNOR-popcount conv.
// grid = B_*HO_ (one block per (batch, output row)), block = 256 (thread = o).
// Packed-x 3-row window lives in smem; all smem reads are warp-broadcast.
// Each thread keeps its 72 weight words in registers.
// 72 XOR + 72 POPC per output (exact minimum), 4 outputs per step, float4 store.
// ---------------------------------------------------------------------------
__global__ void __launch_bounds__(256, 2)
xnor_conv_kernel(float* __restrict__ out) {
    int by = blockIdx.x;
    int b  = by / HO_;
    int y  = by % HO_;
    int o  = threadIdx.x;

    __shared__ __align__(16) unsigned sx[3 * W_ * NWORDS]; // [kh][col][w] 5568 B

    // cooperative load of 3 packed rows (y, y+1, y+2), all 58 columns
    const int ROW4 = W_ * NWORDS / 4; // 116 uint4 per row
    for (int i = threadIdx.x; i < 3 * ROW4; i += 256) {
        int kh = i / ROW4;
        int r  = i - kh * ROW4;
        const uint4* src = (const uint4*)(g_xpack + ((size_t)(b * H_ + y + kh) * W_) * NWORDS);
        ((uint4*)sx)[kh * ROW4 + r] = src[r];
    }

    // per-thread weights into registers (18 x LDG.128, L2-resident)
    unsigned wt[72];
    {
        const uint4* wp4 = (const uint4*)(g_wpack + o * 72);
#pragma unroll
        for (int i = 0; i < 18; i++) ((uint4*)wt)[i] = wp4[i];
    }
    float a = g_alpha[o];
    __syncthreads();

    float* outp = out + ((size_t)(b * OC_ + o) * HO_ + y) * WO_;

    for (int x0 = 0; x0 < WO_; x0 += 4) {
        int P0 = 0, P1 = 0, P2 = 0, P3 = 0;
#pragma unroll
        for (int kh = 0; kh < 3; kh++) {
#pragma unroll
            for (int j = 0; j < 6; j++) {          // 6 pixel columns feed 4 outputs
                const unsigned* px = &sx[(kh * W_ + x0 + j) * NWORDS];
                uint4 plo = *(const uint4*)(px);
                uint4 phi = *(const uint4*)(px + 4);
                unsigned p[8] = {plo.x, plo.y, plo.z, plo.w,
                                 phi.x, phi.y, phi.z, phi.w};
#pragma unroll
                for (int kw = 0; kw < 3; kw++) {
                    int xi = j - kw;
                    if (xi >= 0 && xi < 4) {
                        const unsigned* ww = &wt[(kh * 3 + kw) * NWORDS];
                        int s = 0;
#pragma unroll
                        for (int w = 0; w < 8; w++)
                            s += __popc(p[w] ^ ww[w]);
                        if (xi == 0) P0 += s;
                        else if (xi == 1) P1 += s;
                        else if (xi == 2) P2 += s;
                        else P3 += s;
                    }
                }
            }
        }
        float4 r;
        r.x = a * (float)(CN_ - 2 * P0);
        r.y = a * (float)(CN_ - 2 * P1);
        r.z = a * (float)(CN_ - 2 * P2);
        r.w = a * (float)(CN_ - 2 * P3);
        *(float4*)(outp + x0) = r;
    }
}

// ---------------------------------------------------------------------------
extern "C" void kernel_launch(void* const* d_in, const int* in_sizes, int n_in,
                              void* d_out, int out_size) {
    const float* x   = (const float*)d_in[0];
    const float* wgt = (const float*)d_in[1];
    float* out = (float*)d_out;

    // Pass 1: pack activations
    dim3 g1(B_ * NWORDS, (HW_ + 255) / 256);
    pack_x_kernel<<<g1, 256>>>(x);

    // Pass 2: pack weights + alpha
    pack_w_kernel<<<OC_, 256>>>(wgt);

    // Pass 3: conv
    xnor_conv_kernel<<<B_ * HO_, 256>>>(out);
}